// round 7
// baseline (speedup 1.0000x reference)
#include <cuda_runtime.h>
#include <cuda_fp16.h>
#include <cstdint>

// ---------------- problem constants ----------------
#define M_TOTAL 8192
#define K_DIM   4096
#define N_DIM   4096
#define LRANK   16

#define TM 128
#define TN 256
#define KC 64                     // fp16 elems per k-chunk (128B rows, SW128)
#define NCHUNK (K_DIM / KC)       // 64
#define MT (M_TOTAL / TM)         // 64
#define NT (N_DIM / TN)           // 16

#define A_BLK 16384               // 128x64 fp16
#define W_BLK 32768               // 256x64 fp16
#define STAGE_BYTES 49152         // A_BLK + W_BLK
#define NSTAGE 3
#define SMEM_TOTAL (NSTAGE * STAGE_BYTES)   // 147456 -> 1 CTA/SM

// pre-converted, pre-swizzled operands (device globals = sanctioned scratch)
__device__ __align__(1024) unsigned char g_x[(size_t)MT * NCHUNK * A_BLK]; // 64MB
__device__ __align__(1024) unsigned char g_w[(size_t)NT * NCHUNK * W_BLK]; // 32MB

static __device__ __forceinline__ uint32_t smem_u32(const void* p) {
    uint32_t a;
    asm("{ .reg .u64 t; cvta.to.shared.u64 t, %1; cvt.u32.u64 %0, t; }" : "=r"(a) : "l"(p));
    return a;
}

static __device__ __forceinline__ void cp16(uint32_t dst, const void* src) {
    asm volatile("cp.async.cg.shared.global [%0], [%1], 16;" :: "r"(dst), "l"(src) : "memory");
}

#define LDSM_X4(r0, r1, r2, r3, addr)                                          \
    asm volatile("ldmatrix.sync.aligned.m8n8.x4.shared.b16 {%0,%1,%2,%3}, [%4];" \
        : "=r"(r0), "=r"(r1), "=r"(r2), "=r"(r3) : "r"(addr))

#define MMA16816(d, a0, a1, a2, a3, b0, b1)                                    \
    asm volatile("mma.sync.aligned.m16n8k16.row.col.f32.f16.f16.f32 "          \
        "{%0,%1,%2,%3}, {%4,%5,%6,%7}, {%8,%9}, {%0,%1,%2,%3};"                \
        : "+f"((d)[0]), "+f"((d)[1]), "+f"((d)[2]), "+f"((d)[3])               \
        : "r"(a0), "r"(a1), "r"(a2), "r"(a3), "r"(b0), "r"(b1))

// ===========================================================================
// conv_x: x fp32 -> fp16, SW128-swizzled 128x64 blocks
// ===========================================================================
__global__ __launch_bounds__(256)
void conv_x_kernel(const float* __restrict__ x)
{
    const int kc = blockIdx.x, mt = blockIdx.y;
    const int k0 = kc * KC, m0 = mt * TM;
    unsigned char* blk = g_x + ((size_t)(mt * NCHUNK + kc) * A_BLK);
    const int t = threadIdx.x;
    #pragma unroll
    for (int i = 0; i < (TM * KC) / 256; i++) {
        int e = t + 256 * i;
        int r = e >> 6, c = e & 63;
        float v = x[(size_t)(m0 + r) * K_DIM + k0 + c];
        uint32_t off = (uint32_t)r * 128 + (uint32_t)c * 2;
        uint32_t sw = off ^ ((off >> 3) & 0x70);
        *(__half*)(blk + sw) = __float2half_rn(v);
    }
}

// ===========================================================================
// conv_w: W' = W + B@A -> fp16, SW128-swizzled 256x64 blocks
// grid (NCHUNK, 64): each block does 64 n-rows x 64 k-cols
// n_tile = by>>2 (256-row tiles), row_base = (by&3)*64
// ===========================================================================
__global__ __launch_bounds__(256)
void conv_w_kernel(const float* __restrict__ W, const float* __restrict__ Amat,
                   const float* __restrict__ Bmat)
{
    __shared__ float As[16][64];
    __shared__ float Bs[64][16];
    const int kc = blockIdx.x, by = blockIdx.y;
    const int k0 = kc * KC, n0 = by * 64;
    const int t = threadIdx.x;

    {   // A slab 16x64
        int r = t / 16, c4 = (t % 16) * 4;
        float4 v = *(const float4*)&Amat[(size_t)r * K_DIM + k0 + c4];
        As[r][c4+0] = v.x; As[r][c4+1] = v.y; As[r][c4+2] = v.z; As[r][c4+3] = v.w;
    }
    {   // B slab 64x16
        int nl = t / 4, r4 = (t % 4) * 4;
        float4 v = *(const float4*)&Bmat[(size_t)(n0 + nl) * LRANK + r4];
        Bs[nl][r4+0] = v.x; Bs[nl][r4+1] = v.y; Bs[nl][r4+2] = v.z; Bs[nl][r4+3] = v.w;
    }
    __syncthreads();

    const int n_tile = by >> 2;            // 256-row tiles
    const int row_base = (by & 3) * 64;
    unsigned char* blk = g_w + ((size_t)(n_tile * NCHUNK + kc) * W_BLK);

    #pragma unroll
    for (int i = 0; i < 16; i++) {
        int e = t + 256 * i;
        int rl = e >> 6, c = e & 63;
        float acc = W[(size_t)(n0 + rl) * K_DIM + k0 + c];
        #pragma unroll
        for (int r = 0; r < 16; r++) acc += Bs[rl][r] * As[r][c];
        uint32_t off = (uint32_t)(row_base + rl) * 128 + (uint32_t)c * 2;
        uint32_t sw = off ^ ((off >> 3) & 0x70);
        *(__half*)(blk + sw) = __float2half_rn(acc);
    }
}

// ===========================================================================
// GEMM: out = x @ W'^T + bias  via fp16 HMMA (mma.sync)
// CTA 128x256, 16 warps (4x4), warp tile 32x64, 3-stage, 1 barrier/chunk
// ===========================================================================
__global__ __launch_bounds__(512, 1)
void gemm_mma_kernel(const float* __restrict__ bias, float* __restrict__ out)
{
    extern __shared__ __align__(1024) unsigned char smem[];
    const uint32_t sbase = smem_u32(smem);
    const int tid  = threadIdx.x;
    const int lane = tid & 31;
    const int wid  = tid >> 5;
    const int wm   = wid & 3;          // 4 m-groups of 32
    const int wn   = wid >> 2;         // 4 n-groups of 64
    const int nt = blockIdx.x, mt = blockIdx.y;
    const int m0 = mt * TM, n0 = nt * TN;

    const unsigned char* ga = g_x + (size_t)(mt * NCHUNK) * A_BLK;
    const unsigned char* gb = g_w + (size_t)(nt * NCHUNK) * W_BLK;

    // ---- per-thread ldmatrix addressing (SW128) ----
    const int aRow = wm * 32 + ((lane >> 3) & 1) * 8 + (lane & 7);
    const uint32_t aKsel = (lane >> 4) * 16;            // +16B for k+8 halves
    const int bRow = wn * 64 + ((lane >> 4) & 1) * 8 + (lane & 7);
    const uint32_t bKsel = ((lane >> 3) & 1) * 16;
    const uint32_t X = (uint32_t)(lane & 7) << 4;       // swizzle XOR (row&7)<<4

    float acc[2][8][4];
    #pragma unroll
    for (int i = 0; i < 2; i++)
        #pragma unroll
        for (int j = 0; j < 8; j++)
            #pragma unroll
            for (int q = 0; q < 4; q++) acc[i][j][q] = 0.f;

    // ---- async copy of one chunk into stage s (512 threads) ----
    auto issue = [&](int c, int s) {
        const unsigned char* srcA = ga + (size_t)c * A_BLK;
        const unsigned char* srcB = gb + (size_t)c * W_BLK;
        uint32_t st = sbase + s * STAGE_BYTES;
        #pragma unroll
        for (int i = 0; i < 2; i++) {                      // A: 16KB
            uint32_t off = (uint32_t)tid * 16 + i * 8192;
            cp16(st + off, srcA + off);
        }
        #pragma unroll
        for (int i = 0; i < 4; i++) {                      // B: 32KB
            uint32_t off = (uint32_t)tid * 16 + i * 8192;
            cp16(st + A_BLK + off, srcB + off);
        }
        asm volatile("cp.async.commit_group;" ::: "memory");
    };

    issue(0, 0);
    issue(1, 1);

    int s = 0, spre = 2;
    for (int c = 0; c < NCHUNK; c++) {
        asm volatile("cp.async.wait_group 1;" ::: "memory");
        __syncthreads();
        // stage spre = (c+2)%3 == (c-1)%3 was fully consumed before this barrier
        if (c + 2 < NCHUNK) issue(c + 2, spre);

        const uint32_t Ahi = sbase + s * STAGE_BYTES;
        const uint32_t Bhi = Ahi + A_BLK;

        #pragma unroll
        for (int ks = 0; ks < 4; ks++) {
            const uint32_t kb = (uint32_t)ks * 32;           // k0*2 bytes
            const uint32_t aoff = (kb + aKsel) ^ X;
            const uint32_t boff = (kb + bKsel) ^ X;

            uint32_t aH[2][4];
            #pragma unroll
            for (int m2 = 0; m2 < 2; m2++) {
                uint32_t rb = (uint32_t)(aRow + 16 * m2) * 128;
                LDSM_X4(aH[m2][0], aH[m2][1], aH[m2][2], aH[m2][3], Ahi + rb + aoff);
            }
            uint32_t bH[4][4];
            #pragma unroll
            for (int n4 = 0; n4 < 4; n4++) {
                uint32_t rb = (uint32_t)(bRow + 16 * n4) * 128;
                LDSM_X4(bH[n4][0], bH[n4][1], bH[n4][2], bH[n4][3], Bhi + rb + boff);
            }

            #pragma unroll
            for (int m2 = 0; m2 < 2; m2++) {
                #pragma unroll
                for (int nj = 0; nj < 8; nj++) {
                    const int g = nj >> 1, h = (nj & 1) * 2;
                    MMA16816(acc[m2][nj], aH[m2][0], aH[m2][1], aH[m2][2], aH[m2][3],
                             bH[g][h], bH[g][h + 1]);
                }
            }
        }

        s = (s == NSTAGE - 1) ? 0 : s + 1;
        spre = (spre == NSTAGE - 1) ? 0 : spre + 1;
    }

    // ---- epilogue: bias + store ----
    const int rrow = m0 + wm * 32 + (lane >> 2);
    const int ncol = n0 + wn * 64 + (lane & 3) * 2;

    float2 bb[8];
    #pragma unroll
    for (int nj = 0; nj < 8; nj++)
        bb[nj] = *(const float2*)&bias[ncol + nj * 8];

    #pragma unroll
    for (int m2 = 0; m2 < 2; m2++) {
        #pragma unroll
        for (int nj = 0; nj < 8; nj++) {
            const int n = ncol + nj * 8;
            size_t r0 = (size_t)(rrow + m2 * 16) * N_DIM + n;
            size_t r1 = r0 + 8 * N_DIM;
            float2 o0, o1;
            o0.x = acc[m2][nj][0] + bb[nj].x;
            o0.y = acc[m2][nj][1] + bb[nj].y;
            o1.x = acc[m2][nj][2] + bb[nj].x;
            o1.y = acc[m2][nj][3] + bb[nj].y;
            *(float2*)&out[r0] = o0;
            *(float2*)&out[r1] = o1;
        }
    }
}

// ===========================================================================
extern "C" void kernel_launch(void* const* d_in, const int* in_sizes, int n_in,
                              void* d_out, int out_size)
{
    (void)in_sizes; (void)n_in; (void)out_size;
    const float* x    = (const float*)d_in[0];
    const float* W    = (const float*)d_in[1];
    const float* bias = (const float*)d_in[2];
    const float* A    = (const float*)d_in[3];
    const float* Bm   = (const float*)d_in[4];
    float* out        = (float*)d_out;

    cudaFuncSetAttribute(gemm_mma_kernel,
                         cudaFuncAttributeMaxDynamicSharedMemorySize, SMEM_TOTAL);

    conv_x_kernel<<<dim3(NCHUNK, MT), 256>>>(x);
    conv_w_kernel<<<dim3(NCHUNK, 64), 256>>>(W, A, Bm);
    gemm_mma_kernel<<<dim3(NT, MT), 512, SMEM_TOTAL>>>(bias, out);
}

// round 8
// speedup vs baseline: 1.0027x; 1.0027x over previous
#include <cuda_runtime.h>
#include <cuda_fp16.h>
#include <cstdint>

// ---------------- problem constants ----------------
#define M_TOTAL 8192
#define K_DIM   4096
#define N_DIM   4096
#define LRANK   16

#define TM 128
#define TN 256
#define KC 64                     // fp16 elems per k-chunk (128B rows, SW128)
#define NCHUNK (K_DIM / KC)       // 64
#define MT (M_TOTAL / TM)         // 64
#define NT (N_DIM / TN)           // 16

#define A_BLK 16384               // 128x64 fp16
#define W_BLK 32768               // 256x64 fp16
#define STAGE_BYTES 49152         // A_BLK + W_BLK
#define NSTAGE 3
#define SMEM_TOTAL (NSTAGE * STAGE_BYTES)   // 147456 -> 1 CTA/SM

// pre-converted, pre-swizzled operands (device globals = sanctioned scratch)
__device__ __align__(1024) unsigned char g_x[(size_t)MT * NCHUNK * A_BLK]; // 64MB
__device__ __align__(1024) unsigned char g_w[(size_t)NT * NCHUNK * W_BLK]; // 32MB

static __device__ __forceinline__ uint32_t smem_u32(const void* p) {
    uint32_t a;
    asm("{ .reg .u64 t; cvta.to.shared.u64 t, %1; cvt.u32.u64 %0, t; }" : "=r"(a) : "l"(p));
    return a;
}

static __device__ __forceinline__ void cp16(uint32_t dst, const void* src) {
    asm volatile("cp.async.cg.shared.global [%0], [%1], 16;" :: "r"(dst), "l"(src) : "memory");
}

#define LDSM_X4(r0, r1, r2, r3, addr)                                          \
    asm volatile("ldmatrix.sync.aligned.m8n8.x4.shared.b16 {%0,%1,%2,%3}, [%4];" \
        : "=r"(r0), "=r"(r1), "=r"(r2), "=r"(r3) : "r"(addr))

#define MMA16816(d, a0, a1, a2, a3, b0, b1)                                    \
    asm volatile("mma.sync.aligned.m16n8k16.row.col.f32.f16.f16.f32 "          \
        "{%0,%1,%2,%3}, {%4,%5,%6,%7}, {%8,%9}, {%0,%1,%2,%3};"                \
        : "+f"((d)[0]), "+f"((d)[1]), "+f"((d)[2]), "+f"((d)[3])               \
        : "r"(a0), "r"(a1), "r"(a2), "r"(a3), "r"(b0), "r"(b1))

// ===========================================================================
// conv_x: x fp32 -> fp16, SW128-swizzled 128x64 blocks
// ===========================================================================
__global__ __launch_bounds__(256)
void conv_x_kernel(const float* __restrict__ x)
{
    const int kc = blockIdx.x, mt = blockIdx.y;
    const int k0 = kc * KC, m0 = mt * TM;
    unsigned char* blk = g_x + ((size_t)(mt * NCHUNK + kc) * A_BLK);
    const int t = threadIdx.x;
    #pragma unroll
    for (int i = 0; i < (TM * KC) / 256; i++) {
        int e = t + 256 * i;
        int r = e >> 6, c = e & 63;
        float v = x[(size_t)(m0 + r) * K_DIM + k0 + c];
        uint32_t off = (uint32_t)r * 128 + (uint32_t)c * 2;
        uint32_t sw = off ^ ((off >> 3) & 0x70);
        *(__half*)(blk + sw) = __float2half_rn(v);
    }
}

// ===========================================================================
// conv_w: W' = W + B@A -> fp16, SW128-swizzled 256x64 blocks
// grid (NCHUNK, 64): each block does 64 n-rows x 64 k-cols
// n_tile = by>>2 (256-row tiles), row_base = (by&3)*64
// ===========================================================================
__global__ __launch_bounds__(256)
void conv_w_kernel(const float* __restrict__ W, const float* __restrict__ Amat,
                   const float* __restrict__ Bmat)
{
    __shared__ float As[16][64];
    __shared__ float Bs[64][16];
    const int kc = blockIdx.x, by = blockIdx.y;
    const int k0 = kc * KC, n0 = by * 64;
    const int t = threadIdx.x;

    {   // A slab 16x64
        int r = t / 16, c4 = (t % 16) * 4;
        float4 v = *(const float4*)&Amat[(size_t)r * K_DIM + k0 + c4];
        As[r][c4+0] = v.x; As[r][c4+1] = v.y; As[r][c4+2] = v.z; As[r][c4+3] = v.w;
    }
    {   // B slab 64x16
        int nl = t / 4, r4 = (t % 4) * 4;
        float4 v = *(const float4*)&Bmat[(size_t)(n0 + nl) * LRANK + r4];
        Bs[nl][r4+0] = v.x; Bs[nl][r4+1] = v.y; Bs[nl][r4+2] = v.z; Bs[nl][r4+3] = v.w;
    }
    __syncthreads();

    const int n_tile = by >> 2;            // 256-row tiles
    const int row_base = (by & 3) * 64;
    unsigned char* blk = g_w + ((size_t)(n_tile * NCHUNK + kc) * W_BLK);

    #pragma unroll
    for (int i = 0; i < 16; i++) {
        int e = t + 256 * i;
        int rl = e >> 6, c = e & 63;
        float acc = W[(size_t)(n0 + rl) * K_DIM + k0 + c];
        #pragma unroll
        for (int r = 0; r < 16; r++) acc += Bs[rl][r] * As[r][c];
        uint32_t off = (uint32_t)(row_base + rl) * 128 + (uint32_t)c * 2;
        uint32_t sw = off ^ ((off >> 3) & 0x70);
        *(__half*)(blk + sw) = __float2half_rn(acc);
    }
}

// ===========================================================================
// GEMM: out = x @ W'^T + bias  via fp16 HMMA (mma.sync)
// CTA 128x256, 16 warps (4x4), warp tile 32x64, 3-stage, 1 barrier/chunk
// ===========================================================================
__global__ __launch_bounds__(512, 1)
void gemm_mma_kernel(const float* __restrict__ bias, float* __restrict__ out)
{
    extern __shared__ __align__(1024) unsigned char smem[];
    const uint32_t sbase = smem_u32(smem);
    const int tid  = threadIdx.x;
    const int lane = tid & 31;
    const int wid  = tid >> 5;
    const int wm   = wid & 3;          // 4 m-groups of 32
    const int wn   = wid >> 2;         // 4 n-groups of 64
    const int nt = blockIdx.x, mt = blockIdx.y;
    const int m0 = mt * TM, n0 = nt * TN;

    const unsigned char* ga = g_x + (size_t)(mt * NCHUNK) * A_BLK;
    const unsigned char* gb = g_w + (size_t)(nt * NCHUNK) * W_BLK;

    // ---- per-thread ldmatrix addressing (SW128) ----
    const int aRow = wm * 32 + ((lane >> 3) & 1) * 8 + (lane & 7);
    const uint32_t aKsel = (lane >> 4) * 16;            // +16B for k+8 halves
    const int bRow = wn * 64 + ((lane >> 4) & 1) * 8 + (lane & 7);
    const uint32_t bKsel = ((lane >> 3) & 1) * 16;
    const uint32_t X = (uint32_t)(lane & 7) << 4;       // swizzle XOR (row&7)<<4

    float acc[2][8][4];
    #pragma unroll
    for (int i = 0; i < 2; i++)
        #pragma unroll
        for (int j = 0; j < 8; j++)
            #pragma unroll
            for (int q = 0; q < 4; q++) acc[i][j][q] = 0.f;

    // ---- async copy of one chunk into stage s (512 threads) ----
    auto issue = [&](int c, int s) {
        const unsigned char* srcA = ga + (size_t)c * A_BLK;
        const unsigned char* srcB = gb + (size_t)c * W_BLK;
        uint32_t st = sbase + s * STAGE_BYTES;
        #pragma unroll
        for (int i = 0; i < 2; i++) {                      // A: 16KB
            uint32_t off = (uint32_t)tid * 16 + i * 8192;
            cp16(st + off, srcA + off);
        }
        #pragma unroll
        for (int i = 0; i < 4; i++) {                      // B: 32KB
            uint32_t off = (uint32_t)tid * 16 + i * 8192;
            cp16(st + A_BLK + off, srcB + off);
        }
        asm volatile("cp.async.commit_group;" ::: "memory");
    };

    issue(0, 0);
    issue(1, 1);

    int s = 0, spre = 2;
    for (int c = 0; c < NCHUNK; c++) {
        asm volatile("cp.async.wait_group 1;" ::: "memory");
        __syncthreads();
        // stage spre = (c+2)%3 == (c-1)%3 was fully consumed before this barrier
        if (c + 2 < NCHUNK) issue(c + 2, spre);

        const uint32_t Ahi = sbase + s * STAGE_BYTES;
        const uint32_t Bhi = Ahi + A_BLK;

        #pragma unroll
        for (int ks = 0; ks < 4; ks++) {
            const uint32_t kb = (uint32_t)ks * 32;           // k0*2 bytes
            const uint32_t aoff = (kb + aKsel) ^ X;
            const uint32_t boff = (kb + bKsel) ^ X;

            uint32_t aH[2][4];
            #pragma unroll
            for (int m2 = 0; m2 < 2; m2++) {
                uint32_t rb = (uint32_t)(aRow + 16 * m2) * 128;
                LDSM_X4(aH[m2][0], aH[m2][1], aH[m2][2], aH[m2][3], Ahi + rb + aoff);
            }
            uint32_t bH[4][4];
            #pragma unroll
            for (int n4 = 0; n4 < 4; n4++) {
                uint32_t rb = (uint32_t)(bRow + 16 * n4) * 128;
                LDSM_X4(bH[n4][0], bH[n4][1], bH[n4][2], bH[n4][3], Bhi + rb + boff);
            }

            #pragma unroll
            for (int m2 = 0; m2 < 2; m2++) {
                #pragma unroll
                for (int nj = 0; nj < 8; nj++) {
                    const int g = nj >> 1, h = (nj & 1) * 2;
                    MMA16816(acc[m2][nj], aH[m2][0], aH[m2][1], aH[m2][2], aH[m2][3],
                             bH[g][h], bH[g][h + 1]);
                }
            }
        }

        s = (s == NSTAGE - 1) ? 0 : s + 1;
        spre = (spre == NSTAGE - 1) ? 0 : spre + 1;
    }

    // ---- epilogue: bias + store ----
    const int rrow = m0 + wm * 32 + (lane >> 2);
    const int ncol = n0 + wn * 64 + (lane & 3) * 2;

    float2 bb[8];
    #pragma unroll
    for (int nj = 0; nj < 8; nj++)
        bb[nj] = *(const float2*)&bias[ncol + nj * 8];

    #pragma unroll
    for (int m2 = 0; m2 < 2; m2++) {
        #pragma unroll
        for (int nj = 0; nj < 8; nj++) {
            const int n = ncol + nj * 8;
            size_t r0 = (size_t)(rrow + m2 * 16) * N_DIM + n;
            size_t r1 = r0 + 8 * N_DIM;
            float2 o0, o1;
            o0.x = acc[m2][nj][0] + bb[nj].x;
            o0.y = acc[m2][nj][1] + bb[nj].y;
            o1.x = acc[m2][nj][2] + bb[nj].x;
            o1.y = acc[m2][nj][3] + bb[nj].y;
            *(float2*)&out[r0] = o0;
            *(float2*)&out[r1] = o1;
        }
    }
}

// ===========================================================================
extern "C" void kernel_launch(void* const* d_in, const int* in_sizes, int n_in,
                              void* d_out, int out_size)
{
    (void)in_sizes; (void)n_in; (void)out_size;
    const float* x    = (const float*)d_in[0];
    const float* W    = (const float*)d_in[1];
    const float* bias = (const float*)d_in[2];
    const float* A    = (const float*)d_in[3];
    const float* Bm   = (const float*)d_in[4];
    float* out        = (float*)d_out;

    cudaFuncSetAttribute(gemm_mma_kernel,
                         cudaFuncAttributeMaxDynamicSharedMemorySize, SMEM_TOTAL);

    conv_x_kernel<<<dim3(NCHUNK, MT), 256>>>(x);
    conv_w_kernel<<<dim3(NCHUNK, 64), 256>>>(W, A, Bm);
    gemm_mma_kernel<<<dim3(NT, MT), 512, SMEM_TOTAL>>>(bias, out);
}

// round 9
// speedup vs baseline: 1.0042x; 1.0016x over previous
#include <cuda_runtime.h>
#include <cuda_fp16.h>
#include <cstdint>

// ---------------- problem constants ----------------
#define M_TOTAL 8192
#define K_DIM   4096
#define N_DIM   4096
#define LRANK   16

#define TM 128
#define TN 256
#define KC 64                     // fp16 elems per k-chunk (128B rows, SW128)
#define NCHUNK (K_DIM / KC)       // 64
#define MT (M_TOTAL / TM)         // 64
#define NT (N_DIM / TN)           // 16

#define A_BLK 16384               // 128x64 fp16
#define W_BLK 32768               // 256x64 fp16
#define STAGE_BYTES 49152         // A_BLK + W_BLK
#define NSTAGE 3
#define SMEM_TOTAL (NSTAGE * STAGE_BYTES)   // 147456 -> 1 CTA/SM

// pre-converted, pre-swizzled operands (device globals = sanctioned scratch)
__device__ __align__(1024) unsigned char g_x[(size_t)MT * NCHUNK * A_BLK]; // 64MB
__device__ __align__(1024) unsigned char g_w[(size_t)NT * NCHUNK * W_BLK]; // 32MB

static __device__ __forceinline__ uint32_t smem_u32(const void* p) {
    uint32_t a;
    asm("{ .reg .u64 t; cvta.to.shared.u64 t, %1; cvt.u32.u64 %0, t; }" : "=r"(a) : "l"(p));
    return a;
}

static __device__ __forceinline__ void cp16(uint32_t dst, const void* src) {
    asm volatile("cp.async.cg.shared.global [%0], [%1], 16;" :: "r"(dst), "l"(src) : "memory");
}

#define LDSM_X4(r0, r1, r2, r3, addr)                                          \
    asm volatile("ldmatrix.sync.aligned.m8n8.x4.shared.b16 {%0,%1,%2,%3}, [%4];" \
        : "=r"(r0), "=r"(r1), "=r"(r2), "=r"(r3) : "r"(addr))

#define MMA16816(d, a0, a1, a2, a3, b0, b1)                                    \
    asm volatile("mma.sync.aligned.m16n8k16.row.col.f32.f16.f16.f32 "          \
        "{%0,%1,%2,%3}, {%4,%5,%6,%7}, {%8,%9}, {%0,%1,%2,%3};"                \
        : "+f"((d)[0]), "+f"((d)[1]), "+f"((d)[2]), "+f"((d)[3])               \
        : "r"(a0), "r"(a1), "r"(a2), "r"(a3), "r"(b0), "r"(b1))

// ===========================================================================
// conv_x: x fp32 -> fp16, SW128-swizzled 128x64 blocks
// ===========================================================================
__global__ __launch_bounds__(256)
void conv_x_kernel(const float* __restrict__ x)
{
    const int kc = blockIdx.x, mt = blockIdx.y;
    const int k0 = kc * KC, m0 = mt * TM;
    unsigned char* blk = g_x + ((size_t)(mt * NCHUNK + kc) * A_BLK);
    const int t = threadIdx.x;
    #pragma unroll
    for (int i = 0; i < (TM * KC) / 256; i++) {
        int e = t + 256 * i;
        int r = e >> 6, c = e & 63;
        float v = x[(size_t)(m0 + r) * K_DIM + k0 + c];
        uint32_t off = (uint32_t)r * 128 + (uint32_t)c * 2;
        uint32_t sw = off ^ ((off >> 3) & 0x70);
        *(__half*)(blk + sw) = __float2half_rn(v);
    }
}

// ===========================================================================
// conv_w: W' = W + B@A -> fp16, SW128-swizzled 256x64 blocks
// grid (NCHUNK, 64): each block does 64 n-rows x 64 k-cols
// n_tile = by>>2 (256-row tiles), row_base = (by&3)*64
// ===========================================================================
__global__ __launch_bounds__(256)
void conv_w_kernel(const float* __restrict__ W, const float* __restrict__ Amat,
                   const float* __restrict__ Bmat)
{
    __shared__ float As[16][64];
    __shared__ float Bs[64][16];
    const int kc = blockIdx.x, by = blockIdx.y;
    const int k0 = kc * KC, n0 = by * 64;
    const int t = threadIdx.x;

    {   // A slab 16x64
        int r = t / 16, c4 = (t % 16) * 4;
        float4 v = *(const float4*)&Amat[(size_t)r * K_DIM + k0 + c4];
        As[r][c4+0] = v.x; As[r][c4+1] = v.y; As[r][c4+2] = v.z; As[r][c4+3] = v.w;
    }
    {   // B slab 64x16
        int nl = t / 4, r4 = (t % 4) * 4;
        float4 v = *(const float4*)&Bmat[(size_t)(n0 + nl) * LRANK + r4];
        Bs[nl][r4+0] = v.x; Bs[nl][r4+1] = v.y; Bs[nl][r4+2] = v.z; Bs[nl][r4+3] = v.w;
    }
    __syncthreads();

    const int n_tile = by >> 2;            // 256-row tiles
    const int row_base = (by & 3) * 64;
    unsigned char* blk = g_w + ((size_t)(n_tile * NCHUNK + kc) * W_BLK);

    #pragma unroll
    for (int i = 0; i < 16; i++) {
        int e = t + 256 * i;
        int rl = e >> 6, c = e & 63;
        float acc = W[(size_t)(n0 + rl) * K_DIM + k0 + c];
        #pragma unroll
        for (int r = 0; r < 16; r++) acc += Bs[rl][r] * As[r][c];
        uint32_t off = (uint32_t)(row_base + rl) * 128 + (uint32_t)c * 2;
        uint32_t sw = off ^ ((off >> 3) & 0x70);
        *(__half*)(blk + sw) = __float2half_rn(acc);
    }
}

// ===========================================================================
// GEMM: out = x @ W'^T + bias  via fp16 HMMA (mma.sync)
// CTA 128x256, 16 warps (4x4), warp tile 32x64, 3-stage, 1 barrier/chunk
// ===========================================================================
__global__ __launch_bounds__(512, 1)
void gemm_mma_kernel(const float* __restrict__ bias, float* __restrict__ out)
{
    extern __shared__ __align__(1024) unsigned char smem[];
    const uint32_t sbase = smem_u32(smem);
    const int tid  = threadIdx.x;
    const int lane = tid & 31;
    const int wid  = tid >> 5;
    const int wm   = wid & 3;          // 4 m-groups of 32
    const int wn   = wid >> 2;         // 4 n-groups of 64
    const int nt = blockIdx.x, mt = blockIdx.y;
    const int m0 = mt * TM, n0 = nt * TN;

    const unsigned char* ga = g_x + (size_t)(mt * NCHUNK) * A_BLK;
    const unsigned char* gb = g_w + (size_t)(nt * NCHUNK) * W_BLK;

    // ---- per-thread ldmatrix addressing (SW128) ----
    const int aRow = wm * 32 + ((lane >> 3) & 1) * 8 + (lane & 7);
    const uint32_t aKsel = (lane >> 4) * 16;            // +16B for k+8 halves
    const int bRow = wn * 64 + ((lane >> 4) & 1) * 8 + (lane & 7);
    const uint32_t bKsel = ((lane >> 3) & 1) * 16;
    const uint32_t X = (uint32_t)(lane & 7) << 4;       // swizzle XOR (row&7)<<4

    float acc[2][8][4];
    #pragma unroll
    for (int i = 0; i < 2; i++)
        #pragma unroll
        for (int j = 0; j < 8; j++)
            #pragma unroll
            for (int q = 0; q < 4; q++) acc[i][j][q] = 0.f;

    // ---- async copy of one chunk into stage s (512 threads) ----
    auto issue = [&](int c, int s) {
        const unsigned char* srcA = ga + (size_t)c * A_BLK;
        const unsigned char* srcB = gb + (size_t)c * W_BLK;
        uint32_t st = sbase + s * STAGE_BYTES;
        #pragma unroll
        for (int i = 0; i < 2; i++) {                      // A: 16KB
            uint32_t off = (uint32_t)tid * 16 + i * 8192;
            cp16(st + off, srcA + off);
        }
        #pragma unroll
        for (int i = 0; i < 4; i++) {                      // B: 32KB
            uint32_t off = (uint32_t)tid * 16 + i * 8192;
            cp16(st + A_BLK + off, srcB + off);
        }
        asm volatile("cp.async.commit_group;" ::: "memory");
    };

    issue(0, 0);
    issue(1, 1);

    int s = 0, spre = 2;
    for (int c = 0; c < NCHUNK; c++) {
        asm volatile("cp.async.wait_group 1;" ::: "memory");
        __syncthreads();
        // stage spre = (c+2)%3 == (c-1)%3 was fully consumed before this barrier
        if (c + 2 < NCHUNK) issue(c + 2, spre);

        const uint32_t Ahi = sbase + s * STAGE_BYTES;
        const uint32_t Bhi = Ahi + A_BLK;

        #pragma unroll
        for (int ks = 0; ks < 4; ks++) {
            const uint32_t kb = (uint32_t)ks * 32;           // k0*2 bytes
            const uint32_t aoff = (kb + aKsel) ^ X;
            const uint32_t boff = (kb + bKsel) ^ X;

            uint32_t aH[2][4];
            #pragma unroll
            for (int m2 = 0; m2 < 2; m2++) {
                uint32_t rb = (uint32_t)(aRow + 16 * m2) * 128;
                LDSM_X4(aH[m2][0], aH[m2][1], aH[m2][2], aH[m2][3], Ahi + rb + aoff);
            }
            uint32_t bH[4][4];
            #pragma unroll
            for (int n4 = 0; n4 < 4; n4++) {
                uint32_t rb = (uint32_t)(bRow + 16 * n4) * 128;
                LDSM_X4(bH[n4][0], bH[n4][1], bH[n4][2], bH[n4][3], Bhi + rb + boff);
            }

            #pragma unroll
            for (int m2 = 0; m2 < 2; m2++) {
                #pragma unroll
                for (int nj = 0; nj < 8; nj++) {
                    const int g = nj >> 1, h = (nj & 1) * 2;
                    MMA16816(acc[m2][nj], aH[m2][0], aH[m2][1], aH[m2][2], aH[m2][3],
                             bH[g][h], bH[g][h + 1]);
                }
            }
        }

        s = (s == NSTAGE - 1) ? 0 : s + 1;
        spre = (spre == NSTAGE - 1) ? 0 : spre + 1;
    }

    // ---- epilogue: bias + store ----
    const int rrow = m0 + wm * 32 + (lane >> 2);
    const int ncol = n0 + wn * 64 + (lane & 3) * 2;

    float2 bb[8];
    #pragma unroll
    for (int nj = 0; nj < 8; nj++)
        bb[nj] = *(const float2*)&bias[ncol + nj * 8];

    #pragma unroll
    for (int m2 = 0; m2 < 2; m2++) {
        #pragma unroll
        for (int nj = 0; nj < 8; nj++) {
            const int n = ncol + nj * 8;
            size_t r0 = (size_t)(rrow + m2 * 16) * N_DIM + n;
            size_t r1 = r0 + 8 * N_DIM;
            float2 o0, o1;
            o0.x = acc[m2][nj][0] + bb[nj].x;
            o0.y = acc[m2][nj][1] + bb[nj].y;
            o1.x = acc[m2][nj][2] + bb[nj].x;
            o1.y = acc[m2][nj][3] + bb[nj].y;
            *(float2*)&out[r0] = o0;
            *(float2*)&out[r1] = o1;
        }
    }
}

// ===========================================================================
extern "C" void kernel_launch(void* const* d_in, const int* in_sizes, int n_in,
                              void* d_out, int out_size)
{
    (void)in_sizes; (void)n_in; (void)out_size;
    const float* x    = (const float*)d_in[0];
    const float* W    = (const float*)d_in[1];
    const float* bias = (const float*)d_in[2];
    const float* A    = (const float*)d_in[3];
    const float* Bm   = (const float*)d_in[4];
    float* out        = (float*)d_out;

    cudaFuncSetAttribute(gemm_mma_kernel,
                         cudaFuncAttributeMaxDynamicSharedMemorySize, SMEM_TOTAL);

    conv_x_kernel<<<dim3(NCHUNK, MT), 256>>>(x);
    conv_w_kernel<<<dim3(NCHUNK, 64), 256>>>(W, A, Bm);
    gemm_mma_kernel<<<dim3(NT, MT), 512, SMEM_TOTAL>>>(bias, out);
}